// round 1
// baseline (speedup 1.0000x reference)
#include <cuda_runtime.h>
#include <cuda_bf16.h>

// Problem constants
#define Bsz 4
#define T 1024
#define C 1024
#define H 16
#define HD 64
#define C3 3072

// Scratch (device globals: allocation-free rule)
__device__ float g_qkv[Bsz * T * C3];   // (B*T, 3C)  48 MB
__device__ float g_y[Bsz * T * C];      // (B*T, C)   16 MB

// ---------------------------------------------------------------------------
// SGEMM with bias: Cmat[m,n] = sum_k A[m,k]*Bm[k,n] + bias[n]
// BM=BN=128, BK=8, 256 threads, 8x8 per thread. M,N,K multiples of tile dims.
// ---------------------------------------------------------------------------
__global__ __launch_bounds__(256) void sgemm_bias_kernel(
    const float* __restrict__ A, const float* __restrict__ Bm,
    const float* __restrict__ bias, float* __restrict__ Cmat,
    int M, int N, int K)
{
    __shared__ float As[8][128];
    __shared__ float Bs[8][128];

    const int tid = threadIdx.x;
    const int tx = tid & 15;          // 0..15 -> 8 cols each
    const int ty = tid >> 4;          // 0..15 -> 8 rows each
    const int brow = blockIdx.y * 128;
    const int bcol = blockIdx.x * 128;

    const int arow  = tid >> 1;            // 0..127
    const int acol4 = (tid & 1) * 4;       // 0 or 4
    const int bkrow = tid >> 5;            // 0..7
    const int bcol4 = (tid & 31) * 4;      // 0..124

    const float* Aptr = A + (size_t)(brow + arow) * K + acol4;
    const float* Bptr = Bm + (size_t)bkrow * N + bcol + bcol4;

    float acc[8][8];
#pragma unroll
    for (int i = 0; i < 8; i++)
#pragma unroll
        for (int j = 0; j < 8; j++) acc[i][j] = 0.0f;

    for (int k0 = 0; k0 < K; k0 += 8) {
        float4 a4 = *(const float4*)(Aptr + k0);
        As[acol4 + 0][arow] = a4.x;
        As[acol4 + 1][arow] = a4.y;
        As[acol4 + 2][arow] = a4.z;
        As[acol4 + 3][arow] = a4.w;
        *(float4*)(&Bs[bkrow][bcol4]) = *(const float4*)(Bptr + (size_t)k0 * N);
        __syncthreads();

#pragma unroll
        for (int kk = 0; kk < 8; kk++) {
            float4 a0 = *(const float4*)(&As[kk][ty * 8]);
            float4 a1 = *(const float4*)(&As[kk][ty * 8 + 4]);
            float4 b0 = *(const float4*)(&Bs[kk][tx * 8]);
            float4 b1 = *(const float4*)(&Bs[kk][tx * 8 + 4]);
            float a[8] = {a0.x, a0.y, a0.z, a0.w, a1.x, a1.y, a1.z, a1.w};
            float b[8] = {b0.x, b0.y, b0.z, b0.w, b1.x, b1.y, b1.z, b1.w};
#pragma unroll
            for (int i = 0; i < 8; i++)
#pragma unroll
                for (int j = 0; j < 8; j++) acc[i][j] += a[i] * b[j];
        }
        __syncthreads();
    }

#pragma unroll
    for (int i = 0; i < 8; i++) {
        int m = brow + ty * 8 + i;
        float* cp = Cmat + (size_t)m * N + bcol + tx * 8;
        const float* bp = bias + bcol + tx * 8;
        float4 r0, r1;
        r0.x = acc[i][0] + bp[0]; r0.y = acc[i][1] + bp[1];
        r0.z = acc[i][2] + bp[2]; r0.w = acc[i][3] + bp[3];
        r1.x = acc[i][4] + bp[4]; r1.y = acc[i][5] + bp[5];
        r1.z = acc[i][6] + bp[6]; r1.w = acc[i][7] + bp[7];
        *(float4*)(cp) = r0;
        *(float4*)(cp + 4) = r1;
    }
}

// ---------------------------------------------------------------------------
// Flash attention: one thread = one query row. Writes y (B,T,H*HD).
// Grid: (T/128, B*H). 128 threads. K/V tiles of 32 keys in smem.
// ---------------------------------------------------------------------------
__global__ __launch_bounds__(128) void flash_attn_kernel(
    const float* __restrict__ qkv, const unsigned char* __restrict__ pad,
    float* __restrict__ y)
{
    __shared__ float Ks[32 * 64];
    __shared__ float Vs[32 * 64];

    const int tid = threadIdx.x;
    const int bh  = blockIdx.y;
    const int b   = bh / H;
    const int h   = bh % H;
    const int qi  = blockIdx.x * 128 + tid;
    const int mrow = b * T + qi;

    const float* qp = qkv + (size_t)mrow * C3 + h * HD;
    float q[64];
#pragma unroll
    for (int i = 0; i < 16; i++) {
        float4 v = *(const float4*)(qp + 4 * i);
        q[4 * i + 0] = v.x; q[4 * i + 1] = v.y;
        q[4 * i + 2] = v.z; q[4 * i + 3] = v.w;
    }

    float o[64];
#pragma unroll
    for (int d = 0; d < 64; d++) o[d] = 0.0f;
    float mval = -1e30f, lsum = 0.0f;

    const int ntiles = blockIdx.x * 4 + 4;  // keys up to q-block end (causal)
    const float* kbp = qkv + (size_t)(b * T) * C3 + C + h * HD;
    const float* vbp = qkv + (size_t)(b * T) * C3 + 2 * C + h * HD;
    const unsigned char* pm = pad + (size_t)mrow * T;

    for (int kt = 0; kt < ntiles; kt++) {
        const int kbase = kt * 32;
        // cooperative tile load: 512 float4 slots each for K and V
#pragma unroll
        for (int i = 0; i < 4; i++) {
            int slot = tid + i * 128;
            int r = slot >> 4;
            int d4 = (slot & 15) * 4;
            *(float4*)(Ks + r * 64 + d4) =
                *(const float4*)(kbp + (size_t)(kbase + r) * C3 + d4);
            *(float4*)(Vs + r * 64 + d4) =
                *(const float4*)(vbp + (size_t)(kbase + r) * C3 + d4);
        }
        __syncthreads();

        if (qi >= kbase) {
            float s[32];
#pragma unroll
            for (int j = 0; j < 32; j++) {
                float a0 = 0.f, a1 = 0.f, a2 = 0.f, a3 = 0.f;
#pragma unroll
                for (int d4 = 0; d4 < 16; d4 += 4) {
                    float4 k0 = *(const float4*)(Ks + j * 64 + (d4 + 0) * 4);
                    float4 k1 = *(const float4*)(Ks + j * 64 + (d4 + 1) * 4);
                    float4 k2 = *(const float4*)(Ks + j * 64 + (d4 + 2) * 4);
                    float4 k3 = *(const float4*)(Ks + j * 64 + (d4 + 3) * 4);
                    a0 += q[(d4+0)*4+0]*k0.x + q[(d4+0)*4+1]*k0.y + q[(d4+0)*4+2]*k0.z + q[(d4+0)*4+3]*k0.w;
                    a1 += q[(d4+1)*4+0]*k1.x + q[(d4+1)*4+1]*k1.y + q[(d4+1)*4+2]*k1.z + q[(d4+1)*4+3]*k1.w;
                    a2 += q[(d4+2)*4+0]*k2.x + q[(d4+2)*4+1]*k2.y + q[(d4+2)*4+2]*k2.z + q[(d4+2)*4+3]*k2.w;
                    a3 += q[(d4+3)*4+0]*k3.x + q[(d4+3)*4+1]*k3.y + q[(d4+3)*4+2]*k3.z + q[(d4+3)*4+3]*k3.w;
                }
                s[j] = (a0 + a1 + a2 + a3) * 0.125f;
            }
            // masks: causal + padding
            union { uint4 u[2]; unsigned char c[32]; } mk;
            mk.u[0] = *(const uint4*)(pm + kbase);
            mk.u[1] = *(const uint4*)(pm + kbase + 16);
            float tmax = -1e30f;
#pragma unroll
            for (int j = 0; j < 32; j++) {
                int kj = kbase + j;
                if (kj > qi || mk.c[j]) s[j] = -1e30f;
                tmax = fmaxf(tmax, s[j]);
            }
            float mnew = fmaxf(mval, tmax);
            if (mnew > -1e29f) {
                float alpha = __expf(mval - mnew);
                float psum = 0.f;
#pragma unroll
                for (int j = 0; j < 32; j++) {
                    float p = __expf(s[j] - mnew);
                    s[j] = p;
                    psum += p;
                }
                lsum = lsum * alpha + psum;
                mval = mnew;
#pragma unroll
                for (int d = 0; d < 64; d++) o[d] *= alpha;
#pragma unroll
                for (int d4 = 0; d4 < 16; d4++) {
#pragma unroll
                    for (int j = 0; j < 32; j++) {
                        float4 v4 = *(const float4*)(Vs + j * 64 + d4 * 4);
                        o[d4 * 4 + 0] += s[j] * v4.x;
                        o[d4 * 4 + 1] += s[j] * v4.y;
                        o[d4 * 4 + 2] += s[j] * v4.z;
                        o[d4 * 4 + 3] += s[j] * v4.w;
                    }
                }
            }
        }
        __syncthreads();
    }

    float inv = (lsum > 0.f) ? (1.0f / lsum) : 0.0f;
    float* yp = y + (size_t)mrow * C + h * HD;
#pragma unroll
    for (int d4 = 0; d4 < 16; d4++) {
        float4 r;
        r.x = o[d4 * 4 + 0] * inv;
        r.y = o[d4 * 4 + 1] * inv;
        r.z = o[d4 * 4 + 2] * inv;
        r.w = o[d4 * 4 + 3] * inv;
        *(float4*)(yp + d4 * 4) = r;
    }
}

// ---------------------------------------------------------------------------
// Head-0 raw logits (scale applied, NO mask -- softmax kernel masks).
// Grid: (T/128 qtiles, T/64 ktiles, B). 128 threads; one thread = one query.
// ---------------------------------------------------------------------------
__global__ __launch_bounds__(128) void att_scores_kernel(
    const float* __restrict__ qkv, float* __restrict__ att)
{
    const int b  = blockIdx.z;
    const int qt = blockIdx.x;
    const int kt = blockIdx.y;
    const int kbase = kt * 64;
    if (kbase > qt * 128 + 127) return;  // fully masked tile; softmax writes 0

    __shared__ float Ks[64 * 64];
    const int tid = threadIdx.x;
#pragma unroll
    for (int i = 0; i < 8; i++) {
        int slot = tid + i * 128;
        int r = slot >> 4;
        int d4 = (slot & 15) * 4;
        *(float4*)(Ks + r * 64 + d4) =
            *(const float4*)(qkv + (size_t)(b * T + kbase + r) * C3 + C + d4);
    }
    const int qi = qt * 128 + tid;
    const float* qp = qkv + (size_t)(b * T + qi) * C3;  // head 0
    float q[64];
#pragma unroll
    for (int i = 0; i < 16; i++) {
        float4 v = *(const float4*)(qp + 4 * i);
        q[4 * i + 0] = v.x; q[4 * i + 1] = v.y;
        q[4 * i + 2] = v.z; q[4 * i + 3] = v.w;
    }
    __syncthreads();

    float* op = att + (size_t)(b * T + qi) * T + kbase;
#pragma unroll
    for (int j0 = 0; j0 < 64; j0 += 4) {
        float sv[4];
#pragma unroll
        for (int jj = 0; jj < 4; jj++) {
            int j = j0 + jj;
            float a0 = 0.f, a1 = 0.f, a2 = 0.f, a3 = 0.f;
#pragma unroll
            for (int d4 = 0; d4 < 16; d4 += 4) {
                float4 k0 = *(const float4*)(Ks + j * 64 + (d4 + 0) * 4);
                float4 k1 = *(const float4*)(Ks + j * 64 + (d4 + 1) * 4);
                float4 k2 = *(const float4*)(Ks + j * 64 + (d4 + 2) * 4);
                float4 k3 = *(const float4*)(Ks + j * 64 + (d4 + 3) * 4);
                a0 += q[(d4+0)*4+0]*k0.x + q[(d4+0)*4+1]*k0.y + q[(d4+0)*4+2]*k0.z + q[(d4+0)*4+3]*k0.w;
                a1 += q[(d4+1)*4+0]*k1.x + q[(d4+1)*4+1]*k1.y + q[(d4+1)*4+2]*k1.z + q[(d4+1)*4+3]*k1.w;
                a2 += q[(d4+2)*4+0]*k2.x + q[(d4+2)*4+1]*k2.y + q[(d4+2)*4+2]*k2.z + q[(d4+2)*4+3]*k2.w;
                a3 += q[(d4+3)*4+0]*k3.x + q[(d4+3)*4+1]*k3.y + q[(d4+3)*4+2]*k3.z + q[(d4+3)*4+3]*k3.w;
            }
            sv[jj] = (a0 + a1 + a2 + a3) * 0.125f;
        }
        float4 r = make_float4(sv[0], sv[1], sv[2], sv[3]);
        *(float4*)(op + j0) = r;
    }
}

// ---------------------------------------------------------------------------
// In-place masked row softmax over att (B*T rows, T cols). Masked -> exactly 0.
// ---------------------------------------------------------------------------
__global__ __launch_bounds__(256) void att_softmax_kernel(
    float* __restrict__ att, const unsigned char* __restrict__ pad)
{
    const int row = blockIdx.x;        // b*T + qi
    const int qi = row & (T - 1);
    float* rp = att + (size_t)row * T;
    const unsigned char* pm = pad + (size_t)row * T;
    const int t = threadIdx.x;

    float x[4];
    float lmax = -1e30f;
#pragma unroll
    for (int i = 0; i < 4; i++) {
        int kj = t + i * 256;
        float v = rp[kj];
        bool m = (kj > qi) || pm[kj];
        x[i] = m ? -1e30f : v;
        lmax = fmaxf(lmax, x[i]);
    }
#pragma unroll
    for (int off = 16; off; off >>= 1)
        lmax = fmaxf(lmax, __shfl_xor_sync(0xFFFFFFFFu, lmax, off));

    __shared__ float sred[8];
    __shared__ float sM, sS;
    const int wid = t >> 5, lane = t & 31;
    if (lane == 0) sred[wid] = lmax;
    __syncthreads();
    if (t == 0) {
        float m = sred[0];
#pragma unroll
        for (int i = 1; i < 8; i++) m = fmaxf(m, sred[i]);
        sM = m;
    }
    __syncthreads();
    const float M = sM;

    float ls = 0.f;
#pragma unroll
    for (int i = 0; i < 4; i++) {
        x[i] = __expf(x[i] - M);   // -1e30 - M -> exp underflows to 0
        ls += x[i];
    }
#pragma unroll
    for (int off = 16; off; off >>= 1)
        ls += __shfl_xor_sync(0xFFFFFFFFu, ls, off);
    if (lane == 0) sred[wid] = ls;
    __syncthreads();
    if (t == 0) {
        float s = 0.f;
#pragma unroll
        for (int i = 0; i < 8; i++) s += sred[i];
        sS = s;
    }
    __syncthreads();
    const float inv = (sS > 0.f) ? (1.0f / sS) : 0.0f;
#pragma unroll
    for (int i = 0; i < 4; i++) rp[t + i * 256] = x[i] * inv;
}

// ---------------------------------------------------------------------------
extern "C" void kernel_launch(void* const* d_in, const int* in_sizes, int n_in,
                              void* d_out, int out_size)
{
    const float* x      = (const float*)d_in[0];
    const float* W_attn = (const float*)d_in[1];
    const float* b_attn = (const float*)d_in[2];
    const float* W_proj = (const float*)d_in[3];
    const float* b_proj = (const float*)d_in[4];
    const unsigned char* pad = (const unsigned char*)d_in[5];

    float* y_out   = (float*)d_out;                      // (B,T,C)
    float* att_out = y_out + (size_t)Bsz * T * C;        // (B,1,T,T)

    float* qkv_ptr = nullptr;
    float* y_ptr = nullptr;
    cudaGetSymbolAddress((void**)&qkv_ptr, g_qkv);
    cudaGetSymbolAddress((void**)&y_ptr, g_y);

    // 1) qkv = x @ W_attn + b_attn        (4096 x 3072 x 1024)
    sgemm_bias_kernel<<<dim3(C3 / 128, (Bsz * T) / 128), 256>>>(
        x, W_attn, b_attn, qkv_ptr, Bsz * T, C3, C);

    // 2) head-0 raw logits + masked softmax -> att output
    att_scores_kernel<<<dim3(T / 128, T / 64, Bsz), 128>>>(qkv_ptr, att_out);
    att_softmax_kernel<<<Bsz * T, 256>>>(att_out, pad);

    // 3) flash attention -> y (B,T,H*HD)
    flash_attn_kernel<<<dim3(T / 128, Bsz * H), 128>>>(qkv_ptr, pad, y_ptr);

    // 4) out = y @ W_proj + b_proj        (4096 x 1024 x 1024)
    sgemm_bias_kernel<<<dim3(C / 128, (Bsz * T) / 128), 256>>>(
        y_ptr, W_proj, b_proj, y_out, Bsz * T, C, C);
}

// round 2
// speedup vs baseline: 1.0067x; 1.0067x over previous
#include <cuda_runtime.h>
#include <cuda_bf16.h>

// Problem constants
#define Bsz 4
#define T 1024
#define C 1024
#define H 16
#define HD 64
#define C3 3072

// Scratch (device globals: allocation-free rule)
__device__ float g_qkv[Bsz * T * C3];   // (B*T, 3C)  48 MB
__device__ float g_y[Bsz * T * C];      // (B*T, C)   16 MB

// ---------------------------------------------------------------------------
// SGEMM with bias: Cmat[m,n] = sum_k A[m,k]*Bm[k,n] + bias[n]
// BM=BN=128, BK=8, 256 threads, 8x8 per thread. M,N,K multiples of tile dims.
// ---------------------------------------------------------------------------
__global__ __launch_bounds__(256) void sgemm_bias_kernel(
    const float* __restrict__ A, const float* __restrict__ Bm,
    const float* __restrict__ bias, float* __restrict__ Cmat,
    int M, int N, int K)
{
    __shared__ float As[8][128];
    __shared__ float Bs[8][128];

    const int tid = threadIdx.x;
    const int tx = tid & 15;          // 0..15 -> 8 cols each
    const int ty = tid >> 4;          // 0..15 -> 8 rows each
    const int brow = blockIdx.y * 128;
    const int bcol = blockIdx.x * 128;

    const int arow  = tid >> 1;            // 0..127
    const int acol4 = (tid & 1) * 4;       // 0 or 4
    const int bkrow = tid >> 5;            // 0..7
    const int bcol4 = (tid & 31) * 4;      // 0..124

    const float* Aptr = A + (size_t)(brow + arow) * K + acol4;
    const float* Bptr = Bm + (size_t)bkrow * N + bcol + bcol4;

    float acc[8][8];
#pragma unroll
    for (int i = 0; i < 8; i++)
#pragma unroll
        for (int j = 0; j < 8; j++) acc[i][j] = 0.0f;

    for (int k0 = 0; k0 < K; k0 += 8) {
        float4 a4 = *(const float4*)(Aptr + k0);
        As[acol4 + 0][arow] = a4.x;
        As[acol4 + 1][arow] = a4.y;
        As[acol4 + 2][arow] = a4.z;
        As[acol4 + 3][arow] = a4.w;
        *(float4*)(&Bs[bkrow][bcol4]) = *(const float4*)(Bptr + (size_t)k0 * N);
        __syncthreads();

#pragma unroll
        for (int kk = 0; kk < 8; kk++) {
            float4 a0 = *(const float4*)(&As[kk][ty * 8]);
            float4 a1 = *(const float4*)(&As[kk][ty * 8 + 4]);
            float4 b0 = *(const float4*)(&Bs[kk][tx * 8]);
            float4 b1 = *(const float4*)(&Bs[kk][tx * 8 + 4]);
            float a[8] = {a0.x, a0.y, a0.z, a0.w, a1.x, a1.y, a1.z, a1.w};
            float b[8] = {b0.x, b0.y, b0.z, b0.w, b1.x, b1.y, b1.z, b1.w};
#pragma unroll
            for (int i = 0; i < 8; i++)
#pragma unroll
                for (int j = 0; j < 8; j++) acc[i][j] += a[i] * b[j];
        }
        __syncthreads();
    }

#pragma unroll
    for (int i = 0; i < 8; i++) {
        int m = brow + ty * 8 + i;
        float* cp = Cmat + (size_t)m * N + bcol + tx * 8;
        const float* bp = bias + bcol + tx * 8;
        float4 r0, r1;
        r0.x = acc[i][0] + bp[0]; r0.y = acc[i][1] + bp[1];
        r0.z = acc[i][2] + bp[2]; r0.w = acc[i][3] + bp[3];
        r1.x = acc[i][4] + bp[4]; r1.y = acc[i][5] + bp[5];
        r1.z = acc[i][6] + bp[6]; r1.w = acc[i][7] + bp[7];
        *(float4*)(cp) = r0;
        *(float4*)(cp + 4) = r1;
    }
}

// ---------------------------------------------------------------------------
// Flash attention: one thread = one query row. Writes y (B,T,H*HD).
// Grid: (T/128, B*H). 128 threads. K/V tiles of 32 keys in smem.
// ---------------------------------------------------------------------------
__global__ __launch_bounds__(128) void flash_attn_kernel(
    const float* __restrict__ qkv, const unsigned char* __restrict__ pad,
    float* __restrict__ y)
{
    __shared__ float Ks[32 * 64];
    __shared__ float Vs[32 * 64];

    const int tid = threadIdx.x;
    const int bh  = blockIdx.y;
    const int b   = bh / H;
    const int h   = bh % H;
    const int qi  = blockIdx.x * 128 + tid;
    const int mrow = b * T + qi;

    const float* qp = qkv + (size_t)mrow * C3 + h * HD;
    float q[64];
#pragma unroll
    for (int i = 0; i < 16; i++) {
        float4 v = *(const float4*)(qp + 4 * i);
        q[4 * i + 0] = v.x; q[4 * i + 1] = v.y;
        q[4 * i + 2] = v.z; q[4 * i + 3] = v.w;
    }

    float o[64];
#pragma unroll
    for (int d = 0; d < 64; d++) o[d] = 0.0f;
    float mval = -1e30f, lsum = 0.0f;

    const int ntiles = blockIdx.x * 4 + 4;  // keys up to q-block end (causal)
    const float* kbp = qkv + (size_t)(b * T) * C3 + C + h * HD;
    const float* vbp = qkv + (size_t)(b * T) * C3 + 2 * C + h * HD;
    const unsigned char* pm = pad + (size_t)mrow * T;

    for (int kt = 0; kt < ntiles; kt++) {
        const int kbase = kt * 32;
        // cooperative tile load: 512 float4 slots each for K and V
#pragma unroll
        for (int i = 0; i < 4; i++) {
            int slot = tid + i * 128;
            int r = slot >> 4;
            int d4 = (slot & 15) * 4;
            *(float4*)(Ks + r * 64 + d4) =
                *(const float4*)(kbp + (size_t)(kbase + r) * C3 + d4);
            *(float4*)(Vs + r * 64 + d4) =
                *(const float4*)(vbp + (size_t)(kbase + r) * C3 + d4);
        }
        __syncthreads();

        if (qi >= kbase) {
            float s[32];
#pragma unroll
            for (int j = 0; j < 32; j++) {
                float a0 = 0.f, a1 = 0.f, a2 = 0.f, a3 = 0.f;
#pragma unroll
                for (int d4 = 0; d4 < 16; d4 += 4) {
                    float4 k0 = *(const float4*)(Ks + j * 64 + (d4 + 0) * 4);
                    float4 k1 = *(const float4*)(Ks + j * 64 + (d4 + 1) * 4);
                    float4 k2 = *(const float4*)(Ks + j * 64 + (d4 + 2) * 4);
                    float4 k3 = *(const float4*)(Ks + j * 64 + (d4 + 3) * 4);
                    a0 += q[(d4+0)*4+0]*k0.x + q[(d4+0)*4+1]*k0.y + q[(d4+0)*4+2]*k0.z + q[(d4+0)*4+3]*k0.w;
                    a1 += q[(d4+1)*4+0]*k1.x + q[(d4+1)*4+1]*k1.y + q[(d4+1)*4+2]*k1.z + q[(d4+1)*4+3]*k1.w;
                    a2 += q[(d4+2)*4+0]*k2.x + q[(d4+2)*4+1]*k2.y + q[(d4+2)*4+2]*k2.z + q[(d4+2)*4+3]*k2.w;
                    a3 += q[(d4+3)*4+0]*k3.x + q[(d4+3)*4+1]*k3.y + q[(d4+3)*4+2]*k3.z + q[(d4+3)*4+3]*k3.w;
                }
                s[j] = (a0 + a1 + a2 + a3) * 0.125f;
            }
            // masks: causal + padding
            union { uint4 u[2]; unsigned char c[32]; } mk;
            mk.u[0] = *(const uint4*)(pm + kbase);
            mk.u[1] = *(const uint4*)(pm + kbase + 16);
            float tmax = -1e30f;
#pragma unroll
            for (int j = 0; j < 32; j++) {
                int kj = kbase + j;
                if (kj > qi || mk.c[j]) s[j] = -1e30f;
                tmax = fmaxf(tmax, s[j]);
            }
            float mnew = fmaxf(mval, tmax);
            if (mnew > -1e29f) {
                float alpha = __expf(mval - mnew);
                float psum = 0.f;
#pragma unroll
                for (int j = 0; j < 32; j++) {
                    float p = __expf(s[j] - mnew);
                    s[j] = p;
                    psum += p;
                }
                lsum = lsum * alpha + psum;
                mval = mnew;
#pragma unroll
                for (int d = 0; d < 64; d++) o[d] *= alpha;
#pragma unroll
                for (int d4 = 0; d4 < 16; d4++) {
#pragma unroll
                    for (int j = 0; j < 32; j++) {
                        float4 v4 = *(const float4*)(Vs + j * 64 + d4 * 4);
                        o[d4 * 4 + 0] += s[j] * v4.x;
                        o[d4 * 4 + 1] += s[j] * v4.y;
                        o[d4 * 4 + 2] += s[j] * v4.z;
                        o[d4 * 4 + 3] += s[j] * v4.w;
                    }
                }
            }
        }
        __syncthreads();
    }

    float inv = (lsum > 0.f) ? (1.0f / lsum) : 0.0f;
    float* yp = y + (size_t)mrow * C + h * HD;
#pragma unroll
    for (int d4 = 0; d4 < 16; d4++) {
        float4 r;
        r.x = o[d4 * 4 + 0] * inv;
        r.y = o[d4 * 4 + 1] * inv;
        r.z = o[d4 * 4 + 2] * inv;
        r.w = o[d4 * 4 + 3] * inv;
        *(float4*)(yp + d4 * 4) = r;
    }
}

// ---------------------------------------------------------------------------
// Head-0 raw logits (scale applied, NO mask -- softmax kernel masks).
// Grid: (T/128 qtiles, T/64 ktiles, B). 128 threads; one thread = one query.
// ---------------------------------------------------------------------------
__global__ __launch_bounds__(128) void att_scores_kernel(
    const float* __restrict__ qkv, float* __restrict__ att)
{
    const int b  = blockIdx.z;
    const int qt = blockIdx.x;
    const int kt = blockIdx.y;
    const int kbase = kt * 64;
    if (kbase > qt * 128 + 127) return;  // fully masked tile; softmax writes 0

    __shared__ float Ks[64 * 64];
    const int tid = threadIdx.x;
#pragma unroll
    for (int i = 0; i < 8; i++) {
        int slot = tid + i * 128;
        int r = slot >> 4;
        int d4 = (slot & 15) * 4;
        *(float4*)(Ks + r * 64 + d4) =
            *(const float4*)(qkv + (size_t)(b * T + kbase + r) * C3 + C + d4);
    }
    const int qi = qt * 128 + tid;
    const float* qp = qkv + (size_t)(b * T + qi) * C3;  // head 0
    float q[64];
#pragma unroll
    for (int i = 0; i < 16; i++) {
        float4 v = *(const float4*)(qp + 4 * i);
        q[4 * i + 0] = v.x; q[4 * i + 1] = v.y;
        q[4 * i + 2] = v.z; q[4 * i + 3] = v.w;
    }
    __syncthreads();

    float* op = att + (size_t)(b * T + qi) * T + kbase;
#pragma unroll
    for (int j0 = 0; j0 < 64; j0 += 4) {
        float sv[4];
#pragma unroll
        for (int jj = 0; jj < 4; jj++) {
            int j = j0 + jj;
            float a0 = 0.f, a1 = 0.f, a2 = 0.f, a3 = 0.f;
#pragma unroll
            for (int d4 = 0; d4 < 16; d4 += 4) {
                float4 k0 = *(const float4*)(Ks + j * 64 + (d4 + 0) * 4);
                float4 k1 = *(const float4*)(Ks + j * 64 + (d4 + 1) * 4);
                float4 k2 = *(const float4*)(Ks + j * 64 + (d4 + 2) * 4);
                float4 k3 = *(const float4*)(Ks + j * 64 + (d4 + 3) * 4);
                a0 += q[(d4+0)*4+0]*k0.x + q[(d4+0)*4+1]*k0.y + q[(d4+0)*4+2]*k0.z + q[(d4+0)*4+3]*k0.w;
                a1 += q[(d4+1)*4+0]*k1.x + q[(d4+1)*4+1]*k1.y + q[(d4+1)*4+2]*k1.z + q[(d4+1)*4+3]*k1.w;
                a2 += q[(d4+2)*4+0]*k2.x + q[(d4+2)*4+1]*k2.y + q[(d4+2)*4+2]*k2.z + q[(d4+2)*4+3]*k2.w;
                a3 += q[(d4+3)*4+0]*k3.x + q[(d4+3)*4+1]*k3.y + q[(d4+3)*4+2]*k3.z + q[(d4+3)*4+3]*k3.w;
            }
            sv[jj] = (a0 + a1 + a2 + a3) * 0.125f;
        }
        float4 r = make_float4(sv[0], sv[1], sv[2], sv[3]);
        *(float4*)(op + j0) = r;
    }
}

// ---------------------------------------------------------------------------
// In-place masked row softmax over att (B*T rows, T cols). Masked -> exactly 0.
// ---------------------------------------------------------------------------
__global__ __launch_bounds__(256) void att_softmax_kernel(
    float* __restrict__ att, const unsigned char* __restrict__ pad)
{
    const int row = blockIdx.x;        // b*T + qi
    const int qi = row & (T - 1);
    float* rp = att + (size_t)row * T;
    const unsigned char* pm = pad + (size_t)row * T;
    const int t = threadIdx.x;

    float x[4];
    float lmax = -1e30f;
#pragma unroll
    for (int i = 0; i < 4; i++) {
        int kj = t + i * 256;
        float v = rp[kj];
        bool m = (kj > qi) || pm[kj];
        x[i] = m ? -1e30f : v;
        lmax = fmaxf(lmax, x[i]);
    }
#pragma unroll
    for (int off = 16; off; off >>= 1)
        lmax = fmaxf(lmax, __shfl_xor_sync(0xFFFFFFFFu, lmax, off));

    __shared__ float sred[8];
    __shared__ float sM, sS;
    const int wid = t >> 5, lane = t & 31;
    if (lane == 0) sred[wid] = lmax;
    __syncthreads();
    if (t == 0) {
        float m = sred[0];
#pragma unroll
        for (int i = 1; i < 8; i++) m = fmaxf(m, sred[i]);
        sM = m;
    }
    __syncthreads();
    const float M = sM;

    float ls = 0.f;
#pragma unroll
    for (int i = 0; i < 4; i++) {
        x[i] = __expf(x[i] - M);   // -1e30 - M -> exp underflows to 0
        ls += x[i];
    }
#pragma unroll
    for (int off = 16; off; off >>= 1)
        ls += __shfl_xor_sync(0xFFFFFFFFu, ls, off);
    if (lane == 0) sred[wid] = ls;
    __syncthreads();
    if (t == 0) {
        float s = 0.f;
#pragma unroll
        for (int i = 0; i < 8; i++) s += sred[i];
        sS = s;
    }
    __syncthreads();
    const float inv = (sS > 0.f) ? (1.0f / sS) : 0.0f;
#pragma unroll
    for (int i = 0; i < 4; i++) rp[t + i * 256] = x[i] * inv;
}

// ---------------------------------------------------------------------------
extern "C" void kernel_launch(void* const* d_in, const int* in_sizes, int n_in,
                              void* d_out, int out_size)
{
    const float* x      = (const float*)d_in[0];
    const float* W_attn = (const float*)d_in[1];
    const float* b_attn = (const float*)d_in[2];
    const float* W_proj = (const float*)d_in[3];
    const float* b_proj = (const float*)d_in[4];
    const unsigned char* pad = (const unsigned char*)d_in[5];

    float* y_out   = (float*)d_out;                      // (B,T,C)
    float* att_out = y_out + (size_t)Bsz * T * C;        // (B,1,T,T)

    float* qkv_ptr = nullptr;
    float* y_ptr = nullptr;
    cudaGetSymbolAddress((void**)&qkv_ptr, g_qkv);
    cudaGetSymbolAddress((void**)&y_ptr, g_y);

    // 1) qkv = x @ W_attn + b_attn        (4096 x 3072 x 1024)
    sgemm_bias_kernel<<<dim3(C3 / 128, (Bsz * T) / 128), 256>>>(
        x, W_attn, b_attn, qkv_ptr, Bsz * T, C3, C);

    // 2) head-0 raw logits + masked softmax -> att output
    att_scores_kernel<<<dim3(T / 128, T / 64, Bsz), 128>>>(qkv_ptr, att_out);
    att_softmax_kernel<<<Bsz * T, 256>>>(att_out, pad);

    // 3) flash attention -> y (B,T,H*HD)
    flash_attn_kernel<<<dim3(T / 128, Bsz * H), 128>>>(qkv_ptr, pad, y_ptr);

    // 4) out = y @ W_proj + b_proj        (4096 x 1024 x 1024)
    sgemm_bias_kernel<<<dim3(C / 128, (Bsz * T) / 128), 256>>>(
        y_ptr, W_proj, b_proj, y_out, Bsz * T, C, C);
}